// round 1
// baseline (speedup 1.0000x reference)
#include <cuda_runtime.h>
#include <math_constants.h>

#define NQ    4096
#define NKV   32768
#define CDIM  256
#define KNN   100
#define CAP   2048
#define TILE  2048
#define QPB   16          // queries (warps) per select block
#define FULLM 0xffffffffu

// ---------------- scratch (static device allocations only) ----------------
__device__ float4 g_kp[NKV];               // packed {x,y,z,|k|^2}
__device__ float  g_bufd[(size_t)NQ * CAP]; // per-query candidate d2
__device__ int    g_bufi[(size_t)NQ * CAP]; // per-query candidate idx
__device__ int    g_topk[(size_t)NQ * KNN];

// ---------------- helpers ----------------
__device__ __forceinline__ int warp_sum_i(int v) {
#pragma unroll
    for (int o = 16; o; o >>= 1) v += __shfl_xor_sync(FULLM, v, o);
    return v;
}
__device__ __forceinline__ float warp_sum_f(float v) {
#pragma unroll
    for (int o = 16; o; o >>= 1) v += __shfl_xor_sync(FULLM, v, o);
    return v;
}
__device__ __forceinline__ float warp_max_f(float v) {
#pragma unroll
    for (int o = 16; o; o >>= 1) v = fmaxf(v, __shfl_xor_sync(FULLM, v, o));
    return v;
}

// kth smallest (k=KNN) among buf[0..cnt) via binary search on float bits.
// All values are >= 0 so uint bit order == float order.
__device__ float warp_kth(const float* bufd, int cnt, int lane) {
    unsigned lo = 0u, hi = 0xffffffffu;
    while (lo < hi) {
        unsigned mid = lo + ((hi - lo) >> 1);
        int c = 0;
        for (int i = lane; i < cnt; i += 32)
            c += (__float_as_uint(bufd[i]) <= mid) ? 1 : 0;
        c = warp_sum_i(c);
        if (c >= KNN) hi = mid; else lo = mid + 1u;
    }
    return __uint_as_float(lo);
}

// keep entries with d <= T, preserving order; returns new count
__device__ int warp_compact_le(float* bufd, int* bufi, int cnt, float T, int lane) {
    int newcnt = 0;
    for (int base = 0; base < cnt; base += 32) {
        int i = base + lane;
        bool valid = (i < cnt);
        float d = valid ? bufd[i] : CUDART_INF_F;
        int   id = valid ? bufi[i] : 0;
        bool keep = valid && (d <= T);
        unsigned m = __ballot_sync(FULLM, keep);
        __syncwarp();
        if (keep) {
            int pos = newcnt + __popc(m & ((1u << lane) - 1u));
            bufd[pos] = d; bufi[pos] = id;
        }
        __syncwarp();
        newcnt += __popc(m);
    }
    return newcnt;
}

// ---------------- kernel 0: pack k_pos ----------------
__global__ void prep_kp(const float* __restrict__ kpos) {
    int i = blockIdx.x * blockDim.x + threadIdx.x;
    if (i < NKV) {
        float x = kpos[3 * i], y = kpos[3 * i + 1], z = kpos[3 * i + 2];
        g_kp[i] = make_float4(x, y, z, fmaf(x, x, fmaf(y, y, z * z)));
    }
}

// ---------------- kernel 1: exact 100-NN select (warp per query) ----------------
__global__ void __launch_bounds__(32 * QPB) knn_select(const float* __restrict__ qpos) {
    __shared__ float4 s_tile[TILE];
    const int lane = threadIdx.x & 31;
    const int warp = threadIdx.x >> 5;
    const int q = blockIdx.x * QPB + warp;

    const float qx = qpos[3 * q], qy = qpos[3 * q + 1], qz = qpos[3 * q + 2];
    const float sq = fmaf(qx, qx, fmaf(qy, qy, qz * qz));
    const float ax = -2.f * qx, ay = -2.f * qy, az = -2.f * qz;

    float* bufd = g_bufd + (size_t)q * CAP;
    int*   bufi = g_bufi + (size_t)q * CAP;
    float thr = CUDART_INF_F;
    int cnt = 0;
    const unsigned lt = (1u << lane) - 1u;

    for (int t0 = 0; t0 < NKV; t0 += TILE) {
        __syncthreads();
        for (int i = threadIdx.x; i < TILE; i += 32 * QPB)
            s_tile[i] = g_kp[t0 + i];
        __syncthreads();

#pragma unroll 4
        for (int i = lane; i < TILE; i += 32) {
            float4 kp = s_tile[i];
            float d = fmaf(ax, kp.x, sq + kp.w);
            d = fmaf(ay, kp.y, d);
            d = fmaf(az, kp.z, d);
            bool pred = (d < thr);
            unsigned m = __ballot_sync(FULLM, pred);
            if (m) {
                if (pred) {
                    int pos = cnt + __popc(m & lt);
                    bufd[pos] = fmaxf(d, 0.f);   // clamp so bit-order trick is valid
                    bufi[pos] = t0 + i;
                }
                cnt += __popc(m);
                if (cnt > CAP - 32) {            // rare: re-select threshold, compact
                    float T = warp_kth(bufd, cnt, lane);
                    cnt = warp_compact_le(bufd, bufi, cnt, T, lane);
                    thr = T;                     // future admits strictly below T (ties lose by index)
                }
            }
        }
    }

    // ---- final exact top-KNN (value order + index tiebreak, matching jax top_k set) ----
    float T = warp_kth(bufd, cnt, lane);
    int c = 0;
    for (int i = lane; i < cnt; i += 32) c += (bufd[i] < T) ? 1 : 0;
    c = warp_sum_i(c);                           // strictly-below count (< KNN)

    int* out = g_topk + (size_t)q * KNN;
    int nlt = 0, nties = 0;
    for (int base = 0; base < cnt; base += 32) {
        int i = base + lane;
        bool valid = (i < cnt);
        float d = valid ? bufd[i] : CUDART_INF_F;
        bool w1 = valid && (d < T);
        unsigned m1 = __ballot_sync(FULLM, w1);
        if (w1) out[nlt + __popc(m1 & lt)] = bufi[i];
        nlt += __popc(m1);
        bool w2 = valid && (d == T);
        unsigned m2 = __ballot_sync(FULLM, w2);
        if (w2) {
            int pos = c + nties + __popc(m2 & lt);
            if (pos < KNN) out[pos] = bufi[i];   // buffer order == index order: lowest-index ties win
        }
        nties += __popc(m2);
    }
}

// ---------------- kernel 2: gather attention + (y=2x) + LayerNorm ----------------
__global__ void __launch_bounds__(CDIM) attn_ln(
    const float* __restrict__ qf, const float* __restrict__ kf,
    const float* __restrict__ vf, const float* __restrict__ gamma,
    const float* __restrict__ beta, float* __restrict__ out)
{
    const int q = blockIdx.x;
    const int lane = threadIdx.x & 31;
    const int warp = threadIdx.x >> 5;

    __shared__ int   s_idx[KNN];
    __shared__ float s_logit[KNN];
    __shared__ float s_p[KNN];
    __shared__ float s_red[8];
    __shared__ float s_mean, s_rstd, s_inv;

    if (threadIdx.x < KNN) s_idx[threadIdx.x] = g_topk[(size_t)q * KNN + threadIdx.x];

    // each warp holds the full q row: 8 channels per lane, coalesced layout c = i*32+lane
    float qr[8];
#pragma unroll
    for (int i = 0; i < 8; i++) qr[i] = qf[(size_t)q * CDIM + i * 32 + lane];
    __syncthreads();

    const float scale = rsqrtf((float)CDIM);

    // QK^T logits: warp per neighbor, strided
    for (int n = warp; n < KNN; n += 8) {
        const float* krow = kf + (size_t)s_idx[n] * CDIM;
        float s = 0.f;
#pragma unroll
        for (int i = 0; i < 8; i++) s = fmaf(qr[i], __ldg(krow + i * 32 + lane), s);
        s = warp_sum_f(s);
        if (lane == 0) s_logit[n] = s * scale;
    }
    __syncthreads();

    // softmax over KNN (warp 0)
    if (warp == 0) {
        float mx = -CUDART_INF_F;
        for (int i = lane; i < KNN; i += 32) mx = fmaxf(mx, s_logit[i]);
        mx = warp_max_f(mx);
        float sum = 0.f;
        for (int i = lane; i < KNN; i += 32) {
            float e = __expf(s_logit[i] - mx);
            s_p[i] = e;
            sum += e;
        }
        sum = warp_sum_f(sum);
        if (lane == 0) s_inv = 1.f / sum;
    }
    __syncthreads();

    // PV: thread = channel
    const int t = threadIdx.x;
    float acc = 0.f;
#pragma unroll 4
    for (int n = 0; n < KNN; n++)
        acc = fmaf(s_p[n], __ldg(vf + (size_t)s_idx[n] * CDIM + t), acc);

    // res is fully overwritten by x, so y = x + x = 2x
    float y = 2.f * acc * s_inv;

    // LayerNorm over CDIM
    float s = warp_sum_f(y);
    if (lane == 0) s_red[warp] = s;
    __syncthreads();
    if (warp == 0) {
        float v = (lane < 8) ? s_red[lane] : 0.f;
        v = warp_sum_f(v);
        if (lane == 0) s_mean = v * (1.f / CDIM);
    }
    __syncthreads();
    float d = y - s_mean;
    float s2 = warp_sum_f(d * d);
    if (lane == 0) s_red[warp] = s2;
    __syncthreads();
    if (warp == 0) {
        float v = (lane < 8) ? s_red[lane] : 0.f;
        v = warp_sum_f(v);
        if (lane == 0) s_rstd = rsqrtf(v * (1.f / CDIM) + 1e-5f);
    }
    __syncthreads();

    out[(size_t)q * CDIM + t] = d * s_rstd * gamma[t] + beta[t];
}

// ---------------- launch ----------------
extern "C" void kernel_launch(void* const* d_in, const int* in_sizes, int n_in,
                              void* d_out, int out_size) {
    (void)in_sizes; (void)n_in; (void)out_size;
    const float* qf    = (const float*)d_in[1];
    const float* kf    = (const float*)d_in[2];
    const float* vf    = (const float*)d_in[3];
    const float* qpos  = (const float*)d_in[4];
    const float* kpos  = (const float*)d_in[5];
    const float* gamma = (const float*)d_in[6];
    const float* beta  = (const float*)d_in[7];

    prep_kp<<<(NKV + 255) / 256, 256>>>(kpos);
    knn_select<<<NQ / QPB, 32 * QPB>>>(qpos);
    attn_ln<<<NQ, CDIM>>>(qf, kf, vf, gamma, beta, (float*)d_out);
}